// round 2
// baseline (speedup 1.0000x reference)
#include <cuda_runtime.h>
#include <cstdint>

#define NLEV 16
#define LOG2T 19
#define TSIZE (1u << LOG2T)
#define TMASK (TSIZE - 1u)
#define P1 2654435761u
#define P2 805459861u

__global__ __launch_bounds__(256) void hashenc_kernel(
    const float* __restrict__ x,
    const float* __restrict__ tables,
    float* __restrict__ out,
    int total)   // N * NLEV
{
    int tid = blockIdx.x * blockDim.x + threadIdx.x;
    if (tid >= total) return;
    int n = tid >> 4;
    int l = tid & 15;

    // load point (broadcast across the 16 threads sharing n)
    float px = __ldg(&x[n * 3 + 0]);
    float py = __ldg(&x[n * 3 + 1]);
    float pz = __ldg(&x[n * 3 + 2]);

    // normalize: clip((x+1)*0.5, 0, 1-1e-6)
    const float HI = 1.0f - 1e-6f;
    float nx = fminf(fmaxf((px + 1.0f) * 0.5f, 0.0f), HI);
    float ny = fminf(fmaxf((py + 1.0f) * 0.5f, 0.0f), HI);
    float nz = fminf(fmaxf((pz + 1.0f) * 0.5f, 0.0f), HI);

    float res = (float)(16 << l);   // exact in fp32 for l<=15
    float sx = nx * res, sy = ny * res, sz = nz * res;
    float fxf = floorf(sx), fyf = floorf(sy), fzf = floorf(sz);
    float fx = sx - fxf, fy = sy - fyf, fz = sz - fzf;

    uint32_t ix = (uint32_t)(int)fxf;
    uint32_t iy = (uint32_t)(int)fyf;
    uint32_t iz = (uint32_t)(int)fzf;

    // hash pieces
    uint32_t hx0 = ix;                 // * 1
    uint32_t hx1 = ix + 1u;
    uint32_t hy0 = iy * P1;
    uint32_t hy1 = (iy + 1u) * P1;
    uint32_t hz0 = iz * P2;
    uint32_t hz1 = (iz + 1u) * P2;
    uint32_t lv = (uint32_t)l;

    // corner order c = ox*4 + oy*2 + oz  (matches OFFSETS)
    uint32_t i0 = (hx0 ^ hy0 ^ hz0 ^ lv) & TMASK;  // 000
    uint32_t i1 = (hx0 ^ hy0 ^ hz1 ^ lv) & TMASK;  // 001
    uint32_t i2 = (hx0 ^ hy1 ^ hz0 ^ lv) & TMASK;  // 010
    uint32_t i3 = (hx0 ^ hy1 ^ hz1 ^ lv) & TMASK;  // 011
    uint32_t i4 = (hx1 ^ hy0 ^ hz0 ^ lv) & TMASK;  // 100
    uint32_t i5 = (hx1 ^ hy0 ^ hz1 ^ lv) & TMASK;  // 101
    uint32_t i6 = (hx1 ^ hy1 ^ hz0 ^ lv) & TMASK;  // 110
    uint32_t i7 = (hx1 ^ hy1 ^ hz1 ^ lv) & TMASK;  // 111

    const float2* __restrict__ tab =
        reinterpret_cast<const float2*>(tables) + (size_t)l * TSIZE;

    // issue all 8 gathers back-to-back (MLP = 8)
    float2 e0 = __ldg(&tab[i0]);
    float2 e1 = __ldg(&tab[i1]);
    float2 e2 = __ldg(&tab[i2]);
    float2 e3 = __ldg(&tab[i3]);
    float2 e4 = __ldg(&tab[i4]);
    float2 e5 = __ldg(&tab[i5]);
    float2 e6 = __ldg(&tab[i6]);
    float2 e7 = __ldg(&tab[i7]);

    float wx0 = 1.0f - fx, wx1 = fx;
    float wy0 = 1.0f - fy, wy1 = fy;
    float wz0 = 1.0f - fz, wz1 = fz;

    // weights with (wx*wy)*wz associativity, matching jnp.prod over last axis
    float w0 = (wx0 * wy0) * wz0;
    float w1 = (wx0 * wy0) * wz1;
    float w2 = (wx0 * wy1) * wz0;
    float w3 = (wx0 * wy1) * wz1;
    float w4 = (wx1 * wy0) * wz0;
    float w5 = (wx1 * wy0) * wz1;
    float w6 = (wx1 * wy1) * wz0;
    float w7 = (wx1 * wy1) * wz1;

    float ox0 = e0.x * w0 + e1.x * w1 + e2.x * w2 + e3.x * w3
              + e4.x * w4 + e5.x * w5 + e6.x * w6 + e7.x * w7;
    float oy0 = e0.y * w0 + e1.y * w1 + e2.y * w2 + e3.y * w3
              + e4.y * w4 + e5.y * w5 + e6.y * w6 + e7.y * w7;

    // out[n, l*2 .. l*2+1] ; 16 consecutive threads -> one 128B line
    reinterpret_cast<float2*>(out)[(size_t)n * NLEV + l] = make_float2(ox0, oy0);
}

extern "C" void kernel_launch(void* const* d_in, const int* in_sizes, int n_in,
                              void* d_out, int out_size)
{
    const float* x      = (const float*)d_in[0];   // [N,3]
    const float* tables = (const float*)d_in[1];   // [16, 2^19, 2]
    float* out          = (float*)d_out;           // [N, 32]
    int N = in_sizes[0] / 3;
    int total = N * NLEV;
    int threads = 256;
    int blocks = (total + threads - 1) / threads;
    hashenc_kernel<<<blocks, threads>>>(x, tables, out, total);
}